// round 12
// baseline (speedup 1.0000x reference)
#include <cuda_runtime.h>
#include <cuda_bf16.h>
#include <cstdint>

#define THREADS 384          // threads per block == rows per tile (12 warps)
#define ROWS    384
#define NB      67           // NUM_BASIS = GRID_SIZE + K = 64 + 3
#define TILE_FLOATS (ROWS * NB)       // 25728
#define TILE_BYTES  (TILE_FLOATS * 4) // 102912 (multiple of 16)

// knot value U[k] for padded knot vector (71 knots):
// U[k] = clamp(k-3, 0, 64) * 0.03125 - 1   (exact fp32 binary values)
__device__ __forceinline__ float knot_at(int k) {
    int kk = k - 3;
    kk = kk < 0 ? 0 : (kk > 64 ? 64 : kk);
    return -1.0f + (float)kk * 0.03125f;
}

__device__ __forceinline__ uint32_t smem_u32(const void* p) {
    uint32_t a;
    asm("{ .reg .u64 t; cvta.to.shared.u64 t, %1; cvt.u32.u64 %0, t; }"
        : "=r"(a) : "l"(p));
    return a;
}

__global__ void __launch_bounds__(THREADS, 2)
spline_basis_kernel(const float* __restrict__ x,
                    float* __restrict__ out,
                    int B)
{
    extern __shared__ __align__(16) float tile[];   // TILE_FLOATS floats

    const int t = threadIdx.x;
    const int block0 = blockIdx.x * ROWS;
    const int row = block0 + t;

    // ---- fused zero + compute + scatter: each thread owns row t of the tile.
    // Row start = t*67 floats; stride 67 mod 32 == 3 -> scalar STS conflict-free.
    float* myrow = tile + t * NB;

    if (row < B) {
        const float xv = x[row];   // LDG issues early, hides under zero loop

        // zero own row
        #pragma unroll
        for (int i = 0; i < NB; i++) myrow[i] = 0.f;

        // cell index j in [0, 63]: grid spacing h = 2/64 = 0.03125
        float u = (xv + 1.0f) * 32.0f;
        int j = (int)floorf(u);
        j = j < 0 ? 0 : (j > 63 ? 63 : j);
        const int m = j + 3;   // knot span: U[m] <= x < U[m+1]

        // Cox-de Boor (NURBS A2.2), degree 3.
        float left1  = xv - knot_at(m);
        float right1 = knot_at(m + 1) - xv;
        float left2  = xv - knot_at(m - 1);
        float right2 = knot_at(m + 2) - xv;
        float left3  = xv - knot_at(m - 2);
        float right3 = knot_at(m + 3) - xv;

        float N0, N1, N2, N3;
        // d = 1
        {
            float temp = 1.0f / (right1 + left1);
            N0 = right1 * temp;
            N1 = left1 * temp;
        }
        // d = 2
        {
            float saved = 0.f;
            float temp = N0 / (right1 + left2);
            N0 = saved + right1 * temp;
            saved = left2 * temp;
            temp = N1 / (right2 + left1);
            N1 = saved + right2 * temp;
            N2 = left1 * temp;
        }
        // d = 3
        {
            float saved = 0.f;
            float temp = N0 / (right1 + left3);
            N0 = saved + right1 * temp;
            saved = left3 * temp;
            temp = N1 / (right2 + left2);
            N1 = saved + right2 * temp;
            saved = left2 * temp;
            temp = N2 / (right3 + left1);
            N2 = saved + right3 * temp;
            N3 = left1 * temp;
        }

        // scatter the 4 nonzero values (same thread owns the row: no sync needed)
        myrow[j + 0] = N0;
        myrow[j + 1] = N1;
        myrow[j + 2] = N2;
        myrow[j + 3] = N3;
    }
    // rows >= B: tile region not stored (TMA size is clamped), no need to zero

    __syncthreads();   // all rows ready before bulk store

    // ---- bulk async store SMEM -> GMEM (TMA engine), evict_first L2 policy
    const long long outBase  = (long long)block0 * NB;
    const long long outTotal = (long long)B * NB;
    const long long remainF  = outTotal - outBase;        // floats to store
    const long long bytesLL  = (remainF >= TILE_FLOATS ? (long long)TILE_BYTES
                                                       : remainF * 4);
    const uint32_t bytes = (uint32_t)bytesLL;

    if ((bytes & 15u) == 0) {
        if (t == 0) {
            asm volatile("fence.proxy.async.shared::cta;" ::: "memory");
            uint32_t s = smem_u32(tile);
            uint64_t policy;
            asm("createpolicy.fractional.L2::evict_first.b64 %0, 1.0;"
                : "=l"(policy));
            asm volatile(
                "cp.async.bulk.global.shared::cta.bulk_group.L2::cache_hint "
                "[%0], [%1], %2, %3;"
                :: "l"(out + outBase), "r"(s), "r"(bytes), "l"(policy)
                : "memory");
            asm volatile("cp.async.bulk.commit_group;" ::: "memory");
            asm volatile("cp.async.bulk.wait_group 0;" ::: "memory");
        }
    } else {
        // generic fallback (not hit for B = 2,000,000)
        for (int i = t; i < (int)remainF && i < TILE_FLOATS; i += THREADS) {
            out[outBase + i] = tile[i];
        }
    }
}

extern "C" void kernel_launch(void* const* d_in, const int* in_sizes, int n_in,
                              void* d_out, int out_size)
{
    const float* x = (const float*)d_in[0];
    float* out = (float*)d_out;
    const int B = in_sizes[0];
    const int grid = (B + ROWS - 1) / ROWS;
    static bool attrSet = false;
    if (!attrSet) {
        cudaFuncSetAttribute(spline_basis_kernel,
                             cudaFuncAttributeMaxDynamicSharedMemorySize,
                             TILE_BYTES);
        attrSet = true;
    }
    spline_basis_kernel<<<grid, THREADS, TILE_BYTES>>>(x, out, B);
}

// round 13
// speedup vs baseline: 1.0004x; 1.0004x over previous
#include <cuda_runtime.h>
#include <cuda_bf16.h>
#include <cstdint>

#define THREADS 256          // threads per block == rows per tile
#define ROWS    256
#define NB      67           // NUM_BASIS = GRID_SIZE + K = 64 + 3
#define TILE_FLOATS (ROWS * NB)       // 17152
#define TILE_BYTES  (TILE_FLOATS * 4) // 68608 (multiple of 16)

// knot value U[k] for padded knot vector (71 knots):
// U[k] = clamp(k-3, 0, 64) * 0.03125 - 1   (exact fp32 binary values)
__device__ __forceinline__ float knot_at(int k) {
    int kk = k - 3;
    kk = kk < 0 ? 0 : (kk > 64 ? 64 : kk);
    return -1.0f + (float)kk * 0.03125f;
}

__device__ __forceinline__ uint32_t smem_u32(const void* p) {
    uint32_t a;
    asm("{ .reg .u64 t; cvta.to.shared.u64 t, %1; cvt.u32.u64 %0, t; }"
        : "=r"(a) : "l"(p));
    return a;
}

__global__ void __launch_bounds__(THREADS, 3)
spline_basis_kernel(const float* __restrict__ x,
                    float* __restrict__ out,
                    int B)
{
    __shared__ __align__(16) float tile[TILE_FLOATS];

    const int t = threadIdx.x;
    const int block0 = blockIdx.x * ROWS;
    const int row = block0 + t;

    // ---- fused zero + compute + scatter: each thread owns row t of the tile.
    // Row start = t*67 floats; stride 67 mod 32 == 3 -> scalar STS conflict-free.
    float* myrow = tile + t * NB;

    if (row < B) {
        const float xv = x[row];   // LDG issues early, hides under zero loop

        // zero own row
        #pragma unroll
        for (int i = 0; i < NB; i++) myrow[i] = 0.f;

        // cell index j in [0, 63]: grid spacing h = 2/64 = 0.03125
        float u = (xv + 1.0f) * 32.0f;
        int j = (int)floorf(u);
        j = j < 0 ? 0 : (j > 63 ? 63 : j);
        const int m = j + 3;   // knot span: U[m] <= x < U[m+1]

        // Cox-de Boor (NURBS A2.2), degree 3.
        float left1  = xv - knot_at(m);
        float right1 = knot_at(m + 1) - xv;
        float left2  = xv - knot_at(m - 1);
        float right2 = knot_at(m + 2) - xv;
        float left3  = xv - knot_at(m - 2);
        float right3 = knot_at(m + 3) - xv;

        float N0, N1, N2, N3;
        // d = 1
        {
            float temp = 1.0f / (right1 + left1);
            N0 = right1 * temp;
            N1 = left1 * temp;
        }
        // d = 2
        {
            float saved = 0.f;
            float temp = N0 / (right1 + left2);
            N0 = saved + right1 * temp;
            saved = left2 * temp;
            temp = N1 / (right2 + left1);
            N1 = saved + right2 * temp;
            N2 = left1 * temp;
        }
        // d = 3
        {
            float saved = 0.f;
            float temp = N0 / (right1 + left3);
            N0 = saved + right1 * temp;
            saved = left3 * temp;
            temp = N1 / (right2 + left2);
            N1 = saved + right2 * temp;
            saved = left2 * temp;
            temp = N2 / (right3 + left1);
            N2 = saved + right3 * temp;
            N3 = left1 * temp;
        }

        // scatter the 4 nonzero values (same thread owns the row: no sync needed)
        myrow[j + 0] = N0;
        myrow[j + 1] = N1;
        myrow[j + 2] = N2;
        myrow[j + 3] = N3;
    }
    // rows >= B: tile region not stored (TMA size is clamped), no need to zero

    __syncthreads();   // all rows ready before bulk store

    // ---- bulk async store SMEM -> GMEM (TMA engine), evict_first L2 policy
    const long long outBase  = (long long)block0 * NB;
    const long long outTotal = (long long)B * NB;
    const long long remainF  = outTotal - outBase;        // floats to store
    const long long bytesLL  = (remainF >= TILE_FLOATS ? (long long)TILE_BYTES
                                                       : remainF * 4);
    const uint32_t bytes = (uint32_t)bytesLL;

    if ((bytes & 15u) == 0) {
        if (t == 0) {
            asm volatile("fence.proxy.async.shared::cta;" ::: "memory");
            uint32_t s = smem_u32(tile);
            uint64_t policy;
            asm("createpolicy.fractional.L2::evict_first.b64 %0, 1.0;"
                : "=l"(policy));
            asm volatile(
                "cp.async.bulk.global.shared::cta.bulk_group.L2::cache_hint "
                "[%0], [%1], %2, %3;"
                :: "l"(out + outBase), "r"(s), "r"(bytes), "l"(policy)
                : "memory");
            asm volatile("cp.async.bulk.commit_group;" ::: "memory");
            asm volatile("cp.async.bulk.wait_group 0;" ::: "memory");
        }
    } else {
        // generic fallback (not hit for B = 2,000,000)
        for (int i = t; i < (int)remainF && i < TILE_FLOATS; i += THREADS) {
            out[outBase + i] = tile[i];
        }
    }
}

extern "C" void kernel_launch(void* const* d_in, const int* in_sizes, int n_in,
                              void* d_out, int out_size)
{
    const float* x = (const float*)d_in[0];
    float* out = (float*)d_out;
    const int B = in_sizes[0];
    const int grid = (B + ROWS - 1) / ROWS;
    spline_basis_kernel<<<grid, THREADS>>>(x, out, B);
}

// round 14
// speedup vs baseline: 1.0163x; 1.0159x over previous
#include <cuda_runtime.h>
#include <cuda_bf16.h>
#include <cstdint>

#define THREADS 256          // threads per block == rows per tile
#define ROWS    256
#define NB      67           // NUM_BASIS = GRID_SIZE + K = 64 + 3
#define TILE_FLOATS (ROWS * NB)       // 17152
#define TILE_BYTES  (TILE_FLOATS * 4) // 68608 (multiple of 16)

// knot value U[k] for padded knot vector (71 knots):
// U[k] = clamp(k-3, 0, 64) * 0.03125 - 1   (exact fp32 binary values)
__device__ __forceinline__ float knot_at(int k) {
    int kk = k - 3;
    kk = kk < 0 ? 0 : (kk > 64 ? 64 : kk);
    return -1.0f + (float)kk * 0.03125f;
}

__device__ __forceinline__ uint32_t smem_u32(const void* p) {
    uint32_t a;
    asm("{ .reg .u64 t; cvta.to.shared.u64 t, %1; cvt.u32.u64 %0, t; }"
        : "=r"(a) : "l"(p));
    return a;
}

__global__ void __launch_bounds__(THREADS, 3)
spline_basis_kernel(const float* __restrict__ x,
                    float* __restrict__ out,
                    int B)
{
    __shared__ __align__(16) float tile[TILE_FLOATS];

    const int t = threadIdx.x;
    const int block0 = blockIdx.x * ROWS;
    const int row = block0 + t;

    // ---- fused zero + compute + scatter: each thread owns row t of the tile.
    // Row start = t*67 floats; stride 67 mod 32 == 3 -> scalar STS conflict-free.
    float* myrow = tile + t * NB;

    if (row < B) {
        const float xv = x[row];   // LDG issues early, hides under zero loop

        // zero own row
        #pragma unroll
        for (int i = 0; i < NB; i++) myrow[i] = 0.f;

        // cell index j in [0, 63]: grid spacing h = 2/64 = 0.03125
        float u = (xv + 1.0f) * 32.0f;
        int j = (int)floorf(u);
        j = j < 0 ? 0 : (j > 63 ? 63 : j);
        const int m = j + 3;   // knot span: U[m] <= x < U[m+1]

        // Cox-de Boor (NURBS A2.2), degree 3.
        float left1  = xv - knot_at(m);
        float right1 = knot_at(m + 1) - xv;
        float left2  = xv - knot_at(m - 1);
        float right2 = knot_at(m + 2) - xv;
        float left3  = xv - knot_at(m - 2);
        float right3 = knot_at(m + 3) - xv;

        float N0, N1, N2, N3;
        // d = 1
        {
            float temp = 1.0f / (right1 + left1);
            N0 = right1 * temp;
            N1 = left1 * temp;
        }
        // d = 2
        {
            float saved = 0.f;
            float temp = N0 / (right1 + left2);
            N0 = saved + right1 * temp;
            saved = left2 * temp;
            temp = N1 / (right2 + left1);
            N1 = saved + right2 * temp;
            N2 = left1 * temp;
        }
        // d = 3
        {
            float saved = 0.f;
            float temp = N0 / (right1 + left3);
            N0 = saved + right1 * temp;
            saved = left3 * temp;
            temp = N1 / (right2 + left2);
            N1 = saved + right2 * temp;
            saved = left2 * temp;
            temp = N2 / (right3 + left1);
            N2 = saved + right3 * temp;
            N3 = left1 * temp;
        }

        // scatter the 4 nonzero values (same thread owns the row: no sync needed)
        myrow[j + 0] = N0;
        myrow[j + 1] = N1;
        myrow[j + 2] = N2;
        myrow[j + 3] = N3;
    }
    // rows >= B: tile region not stored (TMA size is clamped), no need to zero

    __syncthreads();   // all rows ready before bulk store

    // ---- bulk async store SMEM -> GMEM (TMA engine), evict_first L2 policy
    const long long outBase  = (long long)block0 * NB;
    const long long outTotal = (long long)B * NB;
    const long long remainF  = outTotal - outBase;        // floats to store
    const long long bytesLL  = (remainF >= TILE_FLOATS ? (long long)TILE_BYTES
                                                       : remainF * 4);
    const uint32_t bytes = (uint32_t)bytesLL;

    if ((bytes & 15u) == 0) {
        if (t == 0) {
            asm volatile("fence.proxy.async.shared::cta;" ::: "memory");
            uint32_t s = smem_u32(tile);
            uint64_t policy;
            asm("createpolicy.fractional.L2::evict_first.b64 %0, 1.0;"
                : "=l"(policy));
            asm volatile(
                "cp.async.bulk.global.shared::cta.bulk_group.L2::cache_hint "
                "[%0], [%1], %2, %3;"
                :: "l"(out + outBase), "r"(s), "r"(bytes), "l"(policy)
                : "memory");
            asm volatile("cp.async.bulk.commit_group;" ::: "memory");
            asm volatile("cp.async.bulk.wait_group 0;" ::: "memory");
        }
    } else {
        // generic fallback (not hit for B = 2,000,000)
        for (int i = t; i < (int)remainF && i < TILE_FLOATS; i += THREADS) {
            out[outBase + i] = tile[i];
        }
    }
}

extern "C" void kernel_launch(void* const* d_in, const int* in_sizes, int n_in,
                              void* d_out, int out_size)
{
    const float* x = (const float*)d_in[0];
    float* out = (float*)d_out;
    const int B = in_sizes[0];
    const int grid = (B + ROWS - 1) / ROWS;
    spline_basis_kernel<<<grid, THREADS>>>(x, out, B);
}

// round 15
// speedup vs baseline: 1.0207x; 1.0043x over previous
#include <cuda_runtime.h>
#include <cuda_bf16.h>
#include <cstdint>

#define THREADS 256          // threads per block == rows per tile
#define ROWS    256
#define NB      67           // NUM_BASIS = GRID_SIZE + K = 64 + 3
#define TILE_FLOATS (ROWS * NB)       // 17152
#define TILE_BYTES  (TILE_FLOATS * 4) // 68608 (multiple of 16)

// knot value U[k] for padded knot vector (71 knots):
// U[k] = clamp(k-3, 0, 64) * 0.03125 - 1   (exact fp32 binary values)
__device__ __forceinline__ float knot_at(int k) {
    int kk = k - 3;
    kk = kk < 0 ? 0 : (kk > 64 ? 64 : kk);
    return -1.0f + (float)kk * 0.03125f;
}

__device__ __forceinline__ uint32_t smem_u32(const void* p) {
    uint32_t a;
    asm("{ .reg .u64 t; cvta.to.shared.u64 t, %1; cvt.u32.u64 %0, t; }"
        : "=r"(a) : "l"(p));
    return a;
}

__global__ void __launch_bounds__(THREADS, 3)
spline_basis_kernel(const float* __restrict__ x,
                    float* __restrict__ out,
                    int B)
{
    __shared__ __align__(16) float tile[TILE_FLOATS];

    const int t = threadIdx.x;
    const int block0 = blockIdx.x * ROWS;
    const int row = block0 + t;

    // ---- fused zero + compute + scatter: each thread owns row t of the tile.
    // Row start = t*67 floats; stride 67 mod 32 == 3 -> scalar STS conflict-free.
    float* myrow = tile + t * NB;

    if (row < B) {
        const float xv = x[row];   // LDG issues early, hides under zero loop

        // zero own row
        #pragma unroll
        for (int i = 0; i < NB; i++) myrow[i] = 0.f;

        // cell index j in [0, 63]: grid spacing h = 2/64 = 0.03125
        float u = (xv + 1.0f) * 32.0f;
        int j = (int)floorf(u);
        j = j < 0 ? 0 : (j > 63 ? 63 : j);
        const int m = j + 3;   // knot span: U[m] <= x < U[m+1]

        // Cox-de Boor (NURBS A2.2), degree 3.
        float left1  = xv - knot_at(m);
        float right1 = knot_at(m + 1) - xv;
        float left2  = xv - knot_at(m - 1);
        float right2 = knot_at(m + 2) - xv;
        float left3  = xv - knot_at(m - 2);
        float right3 = knot_at(m + 3) - xv;

        float N0, N1, N2, N3;
        // d = 1
        {
            float temp = 1.0f / (right1 + left1);
            N0 = right1 * temp;
            N1 = left1 * temp;
        }
        // d = 2
        {
            float saved = 0.f;
            float temp = N0 / (right1 + left2);
            N0 = saved + right1 * temp;
            saved = left2 * temp;
            temp = N1 / (right2 + left1);
            N1 = saved + right2 * temp;
            N2 = left1 * temp;
        }
        // d = 3
        {
            float saved = 0.f;
            float temp = N0 / (right1 + left3);
            N0 = saved + right1 * temp;
            saved = left3 * temp;
            temp = N1 / (right2 + left2);
            N1 = saved + right2 * temp;
            saved = left2 * temp;
            temp = N2 / (right3 + left1);
            N2 = saved + right3 * temp;
            N3 = left1 * temp;
        }

        // scatter the 4 nonzero values (same thread owns the row: no sync needed)
        myrow[j + 0] = N0;
        myrow[j + 1] = N1;
        myrow[j + 2] = N2;
        myrow[j + 3] = N3;
    }
    // rows >= B: tile region not stored (TMA size is clamped), no need to zero

    __syncthreads();   // all rows ready before bulk store

    // ---- bulk async store SMEM -> GMEM (TMA engine), evict_first L2 policy
    const long long outBase  = (long long)block0 * NB;
    const long long outTotal = (long long)B * NB;
    const long long remainF  = outTotal - outBase;        // floats to store
    const long long bytesLL  = (remainF >= TILE_FLOATS ? (long long)TILE_BYTES
                                                       : remainF * 4);
    const uint32_t bytes = (uint32_t)bytesLL;

    if ((bytes & 15u) == 0) {
        if (t == 0) {
            asm volatile("fence.proxy.async.shared::cta;" ::: "memory");
            uint32_t s = smem_u32(tile);
            uint64_t policy;
            asm("createpolicy.fractional.L2::evict_first.b64 %0, 1.0;"
                : "=l"(policy));
            asm volatile(
                "cp.async.bulk.global.shared::cta.bulk_group.L2::cache_hint "
                "[%0], [%1], %2, %3;"
                :: "l"(out + outBase), "r"(s), "r"(bytes), "l"(policy)
                : "memory");
            asm volatile("cp.async.bulk.commit_group;" ::: "memory");
            asm volatile("cp.async.bulk.wait_group 0;" ::: "memory");
        }
    } else {
        // generic fallback (not hit for B = 2,000,000)
        for (int i = t; i < (int)remainF && i < TILE_FLOATS; i += THREADS) {
            out[outBase + i] = tile[i];
        }
    }
}

extern "C" void kernel_launch(void* const* d_in, const int* in_sizes, int n_in,
                              void* d_out, int out_size)
{
    const float* x = (const float*)d_in[0];
    float* out = (float*)d_out;
    const int B = in_sizes[0];
    const int grid = (B + ROWS - 1) / ROWS;
    spline_basis_kernel<<<grid, THREADS>>>(x, out, B);
}